// round 12
// baseline (speedup 1.0000x reference)
#include <cuda_runtime.h>
#include <cuda_bf16.h>
#include <cstdint>

#define BB 4
#define DD 256
#define NN 4096
#define MM 4096
#define TN 128            // n rows per CTA
#define TM 32             // m cols per tile
#define NMT (MM / TM)     // 128 m-tiles
#define NSTAGE 3
#define L2E 1.4426950408889634f

#define ROW_BYTES 512     // 256 bf16, XOR-swizzled chunks (conflict-free for ldmatrix)
#define B_HALF (TM * ROW_BYTES)          // 16384
#define B_BLOB (2 * B_HALF)              // 32768 (hi then lo)
#define A_HALF (TN * ROW_BYTES)          // 65536

__device__ __align__(16) unsigned char g_B[BB * NMT * B_BLOB];  // 16MB
__device__ __align__(16) float4 g_ytg[BB * MM];                 // (yy*log2e, t0,t1,t2)

// ---------------- helpers ----------------
__device__ __forceinline__ uint32_t smem_u32(const void* p) {
    uint32_t a;
    asm("{ .reg .u64 t; cvta.to.shared.u64 t, %1; cvt.u32.u64 %0, t; }"
        : "=r"(a) : "l"(p));
    return a;
}

#define MBARRIER_INIT(mbar, cnt) \
    asm volatile("mbarrier.init.shared.b64 [%0], %1;" \
                 :: "r"((uint32_t)(mbar)), "r"((uint32_t)(cnt)) : "memory")
#define MBARRIER_EXPECT_TX(mbar, bytes) \
    asm volatile("mbarrier.arrive.expect_tx.shared.b64 _, [%0], %1;" \
                 :: "r"((uint32_t)(mbar)), "r"((uint32_t)(bytes)) : "memory")
#define MBARRIER_ARRIVE(mbar) \
    asm volatile("mbarrier.arrive.shared.b64 _, [%0];" \
                 :: "r"((uint32_t)(mbar)) : "memory")
#define MBARRIER_WAIT_PARITY(mbar, ph) do {                                    \
    uint32_t _m = (uint32_t)(mbar); uint32_t _p = (uint32_t)(ph);               \
    asm volatile(                                                               \
        "{\n\t.reg .pred P1;\n\t"                                               \
        "WL_%=:\n\t"                                                            \
        "mbarrier.try_wait.parity.acquire.cta.shared::cta.b64 P1, [%0], %1, 0x989680;\n\t" \
        "@P1 bra.uni WD_%=;\n\t"                                                \
        "bra.uni WL_%=;\n\t"                                                    \
        "WD_%=:\n\t}"                                                           \
        :: "r"(_m), "r"(_p) : "memory");                                        \
} while (0)

__device__ __forceinline__ void bulk_g2s(uint32_t dst_smem, const void* src,
                                         uint32_t bytes, uint32_t mbar) {
    asm volatile(
        "cp.async.bulk.shared::cluster.global.mbarrier::complete_tx::bytes [%0], [%1], %2, [%3];"
        :: "r"(dst_smem), "l"(src), "r"(bytes), "r"(mbar) : "memory");
}

__device__ __forceinline__ float ex2(float x) {
    float r;
    asm("ex2.approx.f32 %0, %1;" : "=f"(r) : "f"(x));
    return r;
}

#define LDSM_X4(r, addr) \
    asm volatile("ldmatrix.sync.aligned.m8n8.x4.shared.b16 {%0,%1,%2,%3}, [%4];" \
                 : "=r"((r)[0]), "=r"((r)[1]), "=r"((r)[2]), "=r"((r)[3]) \
                 : "r"(addr))

__device__ __forceinline__ void mma_bf16(float (&c)[4],
                                         const uint32_t (&a)[4],
                                         uint32_t b0, uint32_t b1) {
    asm volatile(
        "mma.sync.aligned.m16n8k16.row.col.f32.bf16.bf16.f32 "
        "{%0,%1,%2,%3}, {%4,%5,%6,%7}, {%8,%9}, {%0,%1,%2,%3};"
        : "+f"(c[0]), "+f"(c[1]), "+f"(c[2]), "+f"(c[3])
        : "r"(a[0]), "r"(a[1]), "r"(a[2]), "r"(a[3]), "r"(b0), "r"(b1));
}

__device__ __forceinline__ void split_pair(float f0, float f1,
                                           uint32_t& hi, uint32_t& lo) {
    __nv_bfloat16 h0 = __float2bfloat16(f0);
    __nv_bfloat16 h1 = __float2bfloat16(f1);
    __nv_bfloat16 l0 = __float2bfloat16(f0 - __bfloat162float(h0));
    __nv_bfloat16 l1 = __float2bfloat16(f1 - __bfloat162float(h1));
    hi = (uint32_t)__bfloat16_as_ushort(h0) | ((uint32_t)__bfloat16_as_ushort(h1) << 16);
    lo = (uint32_t)__bfloat16_as_ushort(l0) | ((uint32_t)__bfloat16_as_ushort(l1) << 16);
}

// ======= Kernel 1: tgt_emb -> swizzled bf16 hi/lo blobs (SMEM image) + ytg =======
#define CV_PAD 264
#define CONVB_SMEM ((TM * CV_PAD + TM) * 4)

__global__ void __launch_bounds__(256)
convB_kernel(const float* __restrict__ tgt_emb, const float* __restrict__ tgt) {
    extern __shared__ float cs[];          // [TM][CV_PAD] transpose stage
    float* syy = cs + TM * CV_PAD;
    const int tid = threadIdx.x;
    const int b = blockIdx.y, mt = blockIdx.x, m0 = mt * TM;

    if (tid < TM) syy[tid] = 0.f;
    __syncthreads();

    const float* g = tgt_emb + (size_t)b * DD * MM + m0;
    for (int i = tid; i < DD * TM; i += 256) {
        int d = i >> 5, m = i & 31;
        cs[m * CV_PAD + d] = g[(size_t)d * MM + m];
    }
    __syncthreads();

    unsigned char* outh = g_B + (size_t)(b * NMT + mt) * B_BLOB;
    unsigned char* outl = outh + B_HALF;

    for (int i = tid; i < TM * 32; i += 256) {   // task = (m-row, 16B chunk kg)
        int m = i >> 5, kg = i & 31;
        const float* p = cs + m * CV_PAD + kg * 8;
        float4 v0 = *(const float4*)(p);
        float4 v1 = *(const float4*)(p + 4);
        float part = v0.x * v0.x + v0.y * v0.y + v0.z * v0.z + v0.w * v0.w
                   + v1.x * v1.x + v1.y * v1.y + v1.z * v1.z + v1.w * v1.w;
        atomicAdd(&syy[m], part);

        uint4 hq, lq;
        split_pair(v0.x, v0.y, hq.x, lq.x);
        split_pair(v0.z, v0.w, hq.y, lq.y);
        split_pair(v1.x, v1.y, hq.z, lq.z);
        split_pair(v1.z, v1.w, hq.w, lq.w);

        int byte = m * ROW_BYTES + ((kg ^ (m & 7)) << 4);  // XOR swizzle
        *(uint4*)(outh + byte) = hq;
        *(uint4*)(outl + byte) = lq;
    }
    __syncthreads();
    if (tid < TM) {
        int m = m0 + tid;
        float4 v;
        v.x = L2E * syy[tid];
        v.y = tgt[(size_t)b * 3 * MM + m];
        v.z = tgt[(size_t)b * 3 * MM + MM + m];
        v.w = tgt[(size_t)b * 3 * MM + 2 * MM + m];
        g_ytg[b * MM + m] = v;
    }
}

// ======= Kernel 2: fused HMMA GEMM, A-in-regs, distance-8 accumulator rotation =======
// SMEM: mbar full/empty x3 @0..47, ytg 3x512 @64, A @1664, B stages @132736
#define SM_YTG 64
#define SM_A   1664
#define SM_B   (SM_A + 2 * A_HALF)              // 132736
#define SMEM_MAIN (SM_B + NSTAGE * B_BLOB)      // 231040

struct RowState { float m, s, o0, o1, o2; };

__device__ __forceinline__ void row_update(RowState& st, const float (&lg)[8],
                                           const float4 (&yt)[8]) {
    float tmax = lg[0];
#pragma unroll
    for (int j = 1; j < 8; ++j) tmax = fmaxf(tmax, lg[j]);
    float nm = fmaxf(st.m, tmax);
    float corr = ex2(st.m - nm);
    st.m = nm;
    float ls = 0.f, a0 = 0.f, a1 = 0.f, a2 = 0.f;
#pragma unroll
    for (int j = 0; j < 8; ++j) {
        float p = ex2(lg[j] - nm);
        ls += p;
        a0 += p * yt[j].y;
        a1 += p * yt[j].z;
        a2 += p * yt[j].w;
    }
    st.s = st.s * corr + ls;
    st.o0 = st.o0 * corr + a0;
    st.o1 = st.o1 * corr + a1;
    st.o2 = st.o2 * corr + a2;
}

__device__ __forceinline__ void row_merge(RowState& st, int off) {
    float om = __shfl_xor_sync(0xffffffffu, st.m, off);
    float os = __shfl_xor_sync(0xffffffffu, st.s, off);
    float g0 = __shfl_xor_sync(0xffffffffu, st.o0, off);
    float g1 = __shfl_xor_sync(0xffffffffu, st.o1, off);
    float g2 = __shfl_xor_sync(0xffffffffu, st.o2, off);
    float nm = fmaxf(st.m, om);
    float ca = ex2(st.m - nm), cb = ex2(om - nm);
    st.m = nm;
    st.s = st.s * ca + os * cb;
    st.o0 = st.o0 * ca + g0 * cb;
    st.o1 = st.o1 * ca + g1 * cb;
    st.o2 = st.o2 * ca + g2 * cb;
}

__global__ void __launch_bounds__(256, 1)
corr_mma_kernel(const float* __restrict__ src_emb, float* __restrict__ out) {
    extern __shared__ __align__(16) unsigned char smraw[];
    const uint32_t sb = smem_u32(smraw);
    const int tid = threadIdx.x;
    const int wid = tid >> 5;
    const int lane = tid & 31;
    const int b = blockIdx.y;
    const int n0 = blockIdx.x * TN;

    if (tid == 0) {
#pragma unroll
        for (int s = 0; s < NSTAGE; ++s) {
            MBARRIER_INIT(sb + s * 16, 1);       // full
            MBARRIER_INIT(sb + s * 16 + 8, 8);   // empty: 8 warp arrivals
        }
    }
    __syncthreads();

    const unsigned char* gB = g_B + (size_t)b * NMT * B_BLOB;
    const float4* gY = g_ytg + b * MM;

    // kick off loads for tiles 0..2
    if (tid == 0) {
#pragma unroll
        for (int s = 0; s < NSTAGE; ++s) {
            MBARRIER_EXPECT_TX(sb + s * 16, B_BLOB + 512);
            bulk_g2s(sb + SM_B + s * B_BLOB, gB + (size_t)s * B_BLOB, B_BLOB, sb + s * 16);
            bulk_g2s(sb + SM_YTG + s * 512, gY + s * TM, 512, sb + s * 16);
        }
    }

    // ---- convert A (src_emb rows n0..n0+127, scaled by 2*log2e) into SMEM ----
    {
        unsigned char* Ah = smraw + SM_A;
        unsigned char* Al = Ah + A_HALF;
        const float* gA = src_emb + (size_t)b * DD * NN + n0;
        const float sc = 2.0f * L2E;
        for (int i = tid; i < DD * TN / 2; i += 256) {
            int n = i & 127;
            int dp = i >> 7;             // 0..127, covers d = 2dp, 2dp+1
            float v0 = sc * gA[(size_t)(2 * dp) * NN + n];
            float v1 = sc * gA[(size_t)(2 * dp + 1) * NN + n];
            uint32_t hi, lo;
            split_pair(v0, v1, hi, lo);
            int byte = n * ROW_BYTES + (((dp >> 2) ^ (n & 7)) << 4) + (dp & 3) * 4;
            *(uint32_t*)(Ah + byte) = hi;
            *(uint32_t*)(Al + byte) = lo;
        }
    }
    __syncthreads();

    // ---- A fragments -> registers (persistent across all 128 tiles) ----
    const int q = lane & 3;
    const int r = lane >> 2;
    const uint32_t rowA = wid * 16 + ((lane >> 3) & 1) * 8 + (lane & 7);
    const uint32_t aBase = sb + SM_A + rowA * ROW_BYTES;
    const uint32_t hcA = (uint32_t)(lane >> 4);       // 0/1: k-chunk half
    const uint32_t rswA = rowA & 7;

    uint32_t ahr[16][4], alr[16][4];
#pragma unroll
    for (int s = 0; s < 16; ++s) {
        const uint32_t swA = ((2 * s + hcA) ^ rswA) << 4;
        LDSM_X4(ahr[s], aBase + swA);
        LDSM_X4(alr[s], aBase + swA + A_HALF);
    }

    // B ldmatrix lane bases
    const uint32_t rB0 = (uint32_t)((lane >> 4) * 8 + (lane & 7));  // rows 0..15
    const uint32_t bBase0 = rB0 * ROW_BYTES;
    const uint32_t hcB = (uint32_t)((lane >> 3) & 1);
    const uint32_t rswB = rB0 & 7;

    RowState st0 = {-1e30f, 0.f, 0.f, 0.f, 0.f};
    RowState st1 = {-1e30f, 0.f, 0.f, 0.f, 0.f};

    const float4* ytg_s = (const float4*)(smraw + SM_YTG);

    int stage = 0, phase = 0;
    for (int t = 0; t < NMT; ++t) {
        MBARRIER_WAIT_PARITY(sb + stage * 16, phase);

        const uint32_t bb = sb + SM_B + stage * B_BLOB;

        // two disjoint acc sets (even/odd k-step) -> same-register reuse distance 8
        float acc[8][4];
#pragma unroll
        for (int j = 0; j < 8; ++j)
#pragma unroll
            for (int e = 0; e < 4; ++e) acc[j][e] = 0.f;

#pragma unroll
        for (int sp = 0; sp < 8; ++sp) {
            const int s0 = 2 * sp, s1 = 2 * sp + 1;
            const uint32_t swB0 = ((2 * s0 + hcB) ^ rswB) << 4;
            const uint32_t swB1 = ((2 * s1 + hcB) ^ rswB) << 4;
            uint32_t bhA[4], bh2A[4], blA[4], bl2A[4];
            uint32_t bhB[4], bh2B[4], blB[4], bl2B[4];
            LDSM_X4(bhA, bb + bBase0 + swB0);
            LDSM_X4(bh2A, bb + bBase0 + swB0 + 16 * ROW_BYTES);
            LDSM_X4(bhB, bb + bBase0 + swB1);
            LDSM_X4(bh2B, bb + bBase0 + swB1 + 16 * ROW_BYTES);
            LDSM_X4(blA, bb + bBase0 + swB0 + B_HALF);
            LDSM_X4(bl2A, bb + bBase0 + swB0 + B_HALF + 16 * ROW_BYTES);
            LDSM_X4(blB, bb + bBase0 + swB1 + B_HALF);
            LDSM_X4(bl2B, bb + bBase0 + swB1 + B_HALF + 16 * ROW_BYTES);
            // hi*hi (s0 -> acc0-3, s1 -> acc4-7)
            mma_bf16(acc[0], ahr[s0], bhA[0], bhA[1]);
            mma_bf16(acc[1], ahr[s0], bhA[2], bhA[3]);
            mma_bf16(acc[2], ahr[s0], bh2A[0], bh2A[1]);
            mma_bf16(acc[3], ahr[s0], bh2A[2], bh2A[3]);
            mma_bf16(acc[4], ahr[s1], bhB[0], bhB[1]);
            mma_bf16(acc[5], ahr[s1], bhB[2], bhB[3]);
            mma_bf16(acc[6], ahr[s1], bh2B[0], bh2B[1]);
            mma_bf16(acc[7], ahr[s1], bh2B[2], bh2B[3]);
            // lo*hi
            mma_bf16(acc[0], alr[s0], bhA[0], bhA[1]);
            mma_bf16(acc[1], alr[s0], bhA[2], bhA[3]);
            mma_bf16(acc[2], alr[s0], bh2A[0], bh2A[1]);
            mma_bf16(acc[3], alr[s0], bh2A[2], bh2A[3]);
            mma_bf16(acc[4], alr[s1], bhB[0], bhB[1]);
            mma_bf16(acc[5], alr[s1], bhB[2], bhB[3]);
            mma_bf16(acc[6], alr[s1], bh2B[0], bh2B[1]);
            mma_bf16(acc[7], alr[s1], bh2B[2], bh2B[3]);
            // hi*lo
            mma_bf16(acc[0], ahr[s0], blA[0], blA[1]);
            mma_bf16(acc[1], ahr[s0], blA[2], blA[3]);
            mma_bf16(acc[2], ahr[s0], bl2A[0], bl2A[1]);
            mma_bf16(acc[3], ahr[s0], bl2A[2], bl2A[3]);
            mma_bf16(acc[4], ahr[s1], blB[0], blB[1]);
            mma_bf16(acc[5], ahr[s1], blB[2], blB[3]);
            mma_bf16(acc[6], ahr[s1], bl2B[0], bl2B[1]);
            mma_bf16(acc[7], ahr[s1], bl2B[2], bl2B[3]);
        }

        // merge even/odd k contributions
#pragma unroll
        for (int j = 0; j < 4; ++j)
#pragma unroll
            for (int e = 0; e < 4; ++e) acc[j][e] += acc[4 + j][e];

        // grab this tile's (yy, t0..t2) for my 8 cols before releasing the buffer
        float4 yt[8];
#pragma unroll
        for (int j = 0; j < 4; ++j)
#pragma unroll
            for (int e = 0; e < 2; ++e)
                yt[j * 2 + e] = ytg_s[stage * 32 + j * 8 + q * 2 + e];

        if (lane == 0) MBARRIER_ARRIVE(sb + stage * 16 + 8);  // warp done with buffer

        // producer: refill this stage for tile t+3 once all warps released it
        if (tid == 0 && t + NSTAGE < NMT) {
            MBARRIER_WAIT_PARITY(sb + stage * 16 + 8, phase);
            MBARRIER_EXPECT_TX(sb + stage * 16, B_BLOB + 512);
            bulk_g2s(sb + SM_B + stage * B_BLOB, gB + (size_t)(t + NSTAGE) * B_BLOB,
                     B_BLOB, sb + stage * 16);
            bulk_g2s(sb + SM_YTG + stage * 512, gY + (t + NSTAGE) * TM, 512,
                     sb + stage * 16);
        }

        // ---- per-thread online softmax (rows r0 = wid*16+r, r1 = +8) ----
        float l0[8], l1[8];
#pragma unroll
        for (int j = 0; j < 4; ++j)
#pragma unroll
            for (int e = 0; e < 2; ++e) {
                float yy = yt[j * 2 + e].x;
                l0[j * 2 + e] = acc[j][e] - yy;
                l1[j * 2 + e] = acc[j][2 + e] - yy;
            }
        row_update(st0, l0, yt);
        row_update(st1, l1, yt);

        if (++stage == NSTAGE) { stage = 0; phase ^= 1; }
    }

    // ---- merge across quad (lanes sharing the same rows), write out ----
    row_merge(st0, 1); row_merge(st0, 2);
    row_merge(st1, 1); row_merge(st1, 2);

    if (q == 0) {
        size_t base = (size_t)b * 3 * NN;
        int na = n0 + wid * 16 + r;
        int nb = na + 8;
        float ia = 1.f / st0.s, ib = 1.f / st1.s;
        out[base + na] = st0.o0 * ia;
        out[base + NN + na] = st0.o1 * ia;
        out[base + 2 * NN + na] = st0.o2 * ia;
        out[base + nb] = st1.o0 * ib;
        out[base + NN + nb] = st1.o1 * ib;
        out[base + 2 * NN + nb] = st1.o2 * ib;
    }
}

extern "C" void kernel_launch(void* const* d_in, const int* in_sizes, int n_in,
                              void* d_out, int out_size) {
    // inputs per metadata: [0]=src (unused), [1]=tgt, [2]=src_emb, [3]=tgt_emb
    const float* tgt     = (const float*)d_in[1];
    const float* src_emb = (const float*)d_in[2];
    const float* tgt_emb = (const float*)d_in[3];
    float* out = (float*)d_out;

    cudaFuncSetAttribute(convB_kernel,
                         cudaFuncAttributeMaxDynamicSharedMemorySize, CONVB_SMEM);
    cudaFuncSetAttribute(corr_mma_kernel,
                         cudaFuncAttributeMaxDynamicSharedMemorySize, SMEM_MAIN);

    convB_kernel<<<dim3(NMT, BB), 256, CONVB_SMEM>>>(tgt_emb, tgt);
    corr_mma_kernel<<<dim3(NN / TN, BB), 256, SMEM_MAIN>>>(src_emb, out);
}

// round 13
// speedup vs baseline: 1.0451x; 1.0451x over previous
#include <cuda_runtime.h>
#include <cuda_bf16.h>
#include <cstdint>

#define BB 4
#define DD 256
#define NN 4096
#define MM 4096
#define TN 128            // n rows per CTA
#define TM 32             // m cols per tile
#define NMT (MM / TM)     // 128 m-tiles
#define NSTAGE 3
#define L2E 1.4426950408889634f
#define SKEW_CYC 1900u    // ~half tile: anti-phase offset for warps 4-7

#define ROW_BYTES 512     // 256 bf16, XOR-swizzled chunks (conflict-free for ldmatrix)
#define B_HALF (TM * ROW_BYTES)          // 16384
#define B_BLOB (2 * B_HALF)              // 32768 (hi then lo)
#define A_HALF (TN * ROW_BYTES)          // 65536

__device__ __align__(16) unsigned char g_B[BB * NMT * B_BLOB];  // 16MB
__device__ __align__(16) float4 g_ytg[BB * MM];                 // (yy*log2e, t0,t1,t2)

// ---------------- helpers ----------------
__device__ __forceinline__ uint32_t smem_u32(const void* p) {
    uint32_t a;
    asm("{ .reg .u64 t; cvta.to.shared.u64 t, %1; cvt.u32.u64 %0, t; }"
        : "=r"(a) : "l"(p));
    return a;
}

#define MBARRIER_INIT(mbar, cnt) \
    asm volatile("mbarrier.init.shared.b64 [%0], %1;" \
                 :: "r"((uint32_t)(mbar)), "r"((uint32_t)(cnt)) : "memory")
#define MBARRIER_EXPECT_TX(mbar, bytes) \
    asm volatile("mbarrier.arrive.expect_tx.shared.b64 _, [%0], %1;" \
                 :: "r"((uint32_t)(mbar)), "r"((uint32_t)(bytes)) : "memory")
#define MBARRIER_ARRIVE(mbar) \
    asm volatile("mbarrier.arrive.shared.b64 _, [%0];" \
                 :: "r"((uint32_t)(mbar)) : "memory")
#define MBARRIER_WAIT_PARITY(mbar, ph) do {                                    \
    uint32_t _m = (uint32_t)(mbar); uint32_t _p = (uint32_t)(ph);               \
    asm volatile(                                                               \
        "{\n\t.reg .pred P1;\n\t"                                               \
        "WL_%=:\n\t"                                                            \
        "mbarrier.try_wait.parity.acquire.cta.shared::cta.b64 P1, [%0], %1, 0x989680;\n\t" \
        "@P1 bra.uni WD_%=;\n\t"                                                \
        "bra.uni WL_%=;\n\t"                                                    \
        "WD_%=:\n\t}"                                                           \
        :: "r"(_m), "r"(_p) : "memory");                                        \
} while (0)

__device__ __forceinline__ void bulk_g2s(uint32_t dst_smem, const void* src,
                                         uint32_t bytes, uint32_t mbar) {
    asm volatile(
        "cp.async.bulk.shared::cluster.global.mbarrier::complete_tx::bytes [%0], [%1], %2, [%3];"
        :: "r"(dst_smem), "l"(src), "r"(bytes), "r"(mbar) : "memory");
}

__device__ __forceinline__ float ex2(float x) {
    float r;
    asm("ex2.approx.f32 %0, %1;" : "=f"(r) : "f"(x));
    return r;
}

__device__ __forceinline__ uint32_t clk() {
    uint32_t c;
    asm volatile("mov.u32 %0, %%clock;" : "=r"(c));
    return c;
}

#define LDSM_X4(r, addr) \
    asm volatile("ldmatrix.sync.aligned.m8n8.x4.shared.b16 {%0,%1,%2,%3}, [%4];" \
                 : "=r"((r)[0]), "=r"((r)[1]), "=r"((r)[2]), "=r"((r)[3]) \
                 : "r"(addr))

__device__ __forceinline__ void mma_bf16(float (&c)[4],
                                         const uint32_t (&a)[4],
                                         uint32_t b0, uint32_t b1) {
    asm volatile(
        "mma.sync.aligned.m16n8k16.row.col.f32.bf16.bf16.f32 "
        "{%0,%1,%2,%3}, {%4,%5,%6,%7}, {%8,%9}, {%0,%1,%2,%3};"
        : "+f"(c[0]), "+f"(c[1]), "+f"(c[2]), "+f"(c[3])
        : "r"(a[0]), "r"(a[1]), "r"(a[2]), "r"(a[3]), "r"(b0), "r"(b1));
}

__device__ __forceinline__ void split_pair(float f0, float f1,
                                           uint32_t& hi, uint32_t& lo) {
    __nv_bfloat16 h0 = __float2bfloat16(f0);
    __nv_bfloat16 h1 = __float2bfloat16(f1);
    __nv_bfloat16 l0 = __float2bfloat16(f0 - __bfloat162float(h0));
    __nv_bfloat16 l1 = __float2bfloat16(f1 - __bfloat162float(h1));
    hi = (uint32_t)__bfloat16_as_ushort(h0) | ((uint32_t)__bfloat16_as_ushort(h1) << 16);
    lo = (uint32_t)__bfloat16_as_ushort(l0) | ((uint32_t)__bfloat16_as_ushort(l1) << 16);
}

// ======= Kernel 1: tgt_emb -> swizzled bf16 hi/lo blobs (SMEM image) + ytg =======
#define CV_PAD 264
#define CONVB_SMEM ((TM * CV_PAD + TM) * 4)

__global__ void __launch_bounds__(256)
convB_kernel(const float* __restrict__ tgt_emb, const float* __restrict__ tgt) {
    extern __shared__ float cs[];          // [TM][CV_PAD] transpose stage
    float* syy = cs + TM * CV_PAD;
    const int tid = threadIdx.x;
    const int b = blockIdx.y, mt = blockIdx.x, m0 = mt * TM;

    if (tid < TM) syy[tid] = 0.f;
    __syncthreads();

    const float* g = tgt_emb + (size_t)b * DD * MM + m0;
    for (int i = tid; i < DD * TM; i += 256) {
        int d = i >> 5, m = i & 31;
        cs[m * CV_PAD + d] = g[(size_t)d * MM + m];
    }
    __syncthreads();

    unsigned char* outh = g_B + (size_t)(b * NMT + mt) * B_BLOB;
    unsigned char* outl = outh + B_HALF;

    for (int i = tid; i < TM * 32; i += 256) {   // task = (m-row, 16B chunk kg)
        int m = i >> 5, kg = i & 31;
        const float* p = cs + m * CV_PAD + kg * 8;
        float4 v0 = *(const float4*)(p);
        float4 v1 = *(const float4*)(p + 4);
        float part = v0.x * v0.x + v0.y * v0.y + v0.z * v0.z + v0.w * v0.w
                   + v1.x * v1.x + v1.y * v1.y + v1.z * v1.z + v1.w * v1.w;
        atomicAdd(&syy[m], part);

        uint4 hq, lq;
        split_pair(v0.x, v0.y, hq.x, lq.x);
        split_pair(v0.z, v0.w, hq.y, lq.y);
        split_pair(v1.x, v1.y, hq.z, lq.z);
        split_pair(v1.z, v1.w, hq.w, lq.w);

        int byte = m * ROW_BYTES + ((kg ^ (m & 7)) << 4);  // XOR swizzle
        *(uint4*)(outh + byte) = hq;
        *(uint4*)(outl + byte) = lq;
    }
    __syncthreads();
    if (tid < TM) {
        int m = m0 + tid;
        float4 v;
        v.x = L2E * syy[tid];
        v.y = tgt[(size_t)b * 3 * MM + m];
        v.z = tgt[(size_t)b * 3 * MM + MM + m];
        v.w = tgt[(size_t)b * 3 * MM + 2 * MM + m];
        g_ytg[b * MM + m] = v;
    }
}

// ======= Kernel 2: fused HMMA GEMM, A-in-regs, anti-phase warp halves =======
// SMEM: mbar full/empty x3 @0..47, ytg 3x512 @64, A @1664, B stages @132736
#define SM_YTG 64
#define SM_A   1664
#define SM_B   (SM_A + 2 * A_HALF)              // 132736
#define SMEM_MAIN (SM_B + NSTAGE * B_BLOB)      // 231040

struct RowState { float m, s, o0, o1, o2; };

__device__ __forceinline__ void row_update(RowState& st, const float (&lg)[8],
                                           const float4 (&yt)[8]) {
    float tmax = lg[0];
#pragma unroll
    for (int j = 1; j < 8; ++j) tmax = fmaxf(tmax, lg[j]);
    float nm = fmaxf(st.m, tmax);
    float corr = ex2(st.m - nm);
    st.m = nm;
    float ls = 0.f, a0 = 0.f, a1 = 0.f, a2 = 0.f;
#pragma unroll
    for (int j = 0; j < 8; ++j) {
        float p = ex2(lg[j] - nm);
        ls += p;
        a0 += p * yt[j].y;
        a1 += p * yt[j].z;
        a2 += p * yt[j].w;
    }
    st.s = st.s * corr + ls;
    st.o0 = st.o0 * corr + a0;
    st.o1 = st.o1 * corr + a1;
    st.o2 = st.o2 * corr + a2;
}

__device__ __forceinline__ void row_merge(RowState& st, int off) {
    float om = __shfl_xor_sync(0xffffffffu, st.m, off);
    float os = __shfl_xor_sync(0xffffffffu, st.s, off);
    float g0 = __shfl_xor_sync(0xffffffffu, st.o0, off);
    float g1 = __shfl_xor_sync(0xffffffffu, st.o1, off);
    float g2 = __shfl_xor_sync(0xffffffffu, st.o2, off);
    float nm = fmaxf(st.m, om);
    float ca = ex2(st.m - nm), cb = ex2(om - nm);
    st.m = nm;
    st.s = st.s * ca + os * cb;
    st.o0 = st.o0 * ca + g0 * cb;
    st.o1 = st.o1 * ca + g1 * cb;
    st.o2 = st.o2 * ca + g2 * cb;
}

__global__ void __launch_bounds__(256, 1)
corr_mma_kernel(const float* __restrict__ src_emb, float* __restrict__ out) {
    extern __shared__ __align__(16) unsigned char smraw[];
    const uint32_t sb = smem_u32(smraw);
    const int tid = threadIdx.x;
    const int wid = tid >> 5;
    const int lane = tid & 31;
    const int b = blockIdx.y;
    const int n0 = blockIdx.x * TN;

    if (tid == 0) {
#pragma unroll
        for (int s = 0; s < NSTAGE; ++s) {
            MBARRIER_INIT(sb + s * 16, 1);       // full
            MBARRIER_INIT(sb + s * 16 + 8, 8);   // empty: 8 warp arrivals
        }
    }
    __syncthreads();

    const unsigned char* gB = g_B + (size_t)b * NMT * B_BLOB;
    const float4* gY = g_ytg + b * MM;

    // kick off loads for tiles 0..2
    if (tid == 0) {
#pragma unroll
        for (int s = 0; s < NSTAGE; ++s) {
            MBARRIER_EXPECT_TX(sb + s * 16, B_BLOB + 512);
            bulk_g2s(sb + SM_B + s * B_BLOB, gB + (size_t)s * B_BLOB, B_BLOB, sb + s * 16);
            bulk_g2s(sb + SM_YTG + s * 512, gY + s * TM, 512, sb + s * 16);
        }
    }

    // ---- convert A (src_emb rows n0..n0+127, scaled by 2*log2e) into SMEM ----
    {
        unsigned char* Ah = smraw + SM_A;
        unsigned char* Al = Ah + A_HALF;
        const float* gA = src_emb + (size_t)b * DD * NN + n0;
        const float sc = 2.0f * L2E;
        for (int i = tid; i < DD * TN / 2; i += 256) {
            int n = i & 127;
            int dp = i >> 7;             // 0..127, covers d = 2dp, 2dp+1
            float v0 = sc * gA[(size_t)(2 * dp) * NN + n];
            float v1 = sc * gA[(size_t)(2 * dp + 1) * NN + n];
            uint32_t hi, lo;
            split_pair(v0, v1, hi, lo);
            int byte = n * ROW_BYTES + (((dp >> 2) ^ (n & 7)) << 4) + (dp & 3) * 4;
            *(uint32_t*)(Ah + byte) = hi;
            *(uint32_t*)(Al + byte) = lo;
        }
    }
    __syncthreads();

    // ---- A fragments -> registers (persistent across all 128 tiles) ----
    const int q = lane & 3;
    const int r = lane >> 2;
    const uint32_t rowA = wid * 16 + ((lane >> 3) & 1) * 8 + (lane & 7);
    const uint32_t aBase = sb + SM_A + rowA * ROW_BYTES;
    const uint32_t hcA = (uint32_t)(lane >> 4);       // 0/1: k-chunk half
    const uint32_t rswA = rowA & 7;

    uint32_t ahr[16][4], alr[16][4];
#pragma unroll
    for (int s = 0; s < 16; ++s) {
        const uint32_t swA = ((2 * s + hcA) ^ rswA) << 4;
        LDSM_X4(ahr[s], aBase + swA);
        LDSM_X4(alr[s], aBase + swA + A_HALF);
    }

    // B ldmatrix lane bases
    const uint32_t rB0 = (uint32_t)((lane >> 4) * 8 + (lane & 7));  // rows 0..15
    const uint32_t bBase0 = rB0 * ROW_BYTES;
    const uint32_t hcB = (uint32_t)((lane >> 3) & 1);
    const uint32_t rswB = rB0 & 7;

    // ---- anti-phase: warps 4-7 start half a tile late so each SMSP's two
    //      warps alternate MMA <-> epilogue instead of running in lockstep ----
    if (wid >= 4) {
        uint32_t c0 = clk();
        while (clk() - c0 < SKEW_CYC) {}
    }

    RowState st0 = {-1e30f, 0.f, 0.f, 0.f, 0.f};
    RowState st1 = {-1e30f, 0.f, 0.f, 0.f, 0.f};

    const float4* ytg_s = (const float4*)(smraw + SM_YTG);

    int stage = 0, phase = 0;
    for (int t = 0; t < NMT; ++t) {
        MBARRIER_WAIT_PARITY(sb + stage * 16, phase);

        const uint32_t bb = sb + SM_B + stage * B_BLOB;

        float acc[4][4];
#pragma unroll
        for (int j = 0; j < 4; ++j)
#pragma unroll
            for (int e = 0; e < 4; ++e) acc[j][e] = 0.f;

#pragma unroll
        for (int s = 0; s < 16; ++s) {
            const uint32_t swB = ((2 * s + hcB) ^ rswB) << 4;
            uint32_t bh[4], bh2[4], bl[4], bl2[4];
            LDSM_X4(bh, bb + bBase0 + swB);
            LDSM_X4(bh2, bb + bBase0 + swB + 16 * ROW_BYTES);
            LDSM_X4(bl, bb + bBase0 + swB + B_HALF);
            LDSM_X4(bl2, bb + bBase0 + swB + B_HALF + 16 * ROW_BYTES);
            mma_bf16(acc[0], ahr[s], bh[0], bh[1]);
            mma_bf16(acc[1], ahr[s], bh[2], bh[3]);
            mma_bf16(acc[2], ahr[s], bh2[0], bh2[1]);
            mma_bf16(acc[3], ahr[s], bh2[2], bh2[3]);
            mma_bf16(acc[0], alr[s], bh[0], bh[1]);
            mma_bf16(acc[1], alr[s], bh[2], bh[3]);
            mma_bf16(acc[2], alr[s], bh2[0], bh2[1]);
            mma_bf16(acc[3], alr[s], bh2[2], bh2[3]);
            mma_bf16(acc[0], ahr[s], bl[0], bl[1]);
            mma_bf16(acc[1], ahr[s], bl[2], bl[3]);
            mma_bf16(acc[2], ahr[s], bl2[0], bl2[1]);
            mma_bf16(acc[3], ahr[s], bl2[2], bl2[3]);
        }

        // grab this tile's (yy, t0..t2) for my 8 cols before releasing the buffer
        float4 yt[8];
#pragma unroll
        for (int j = 0; j < 4; ++j)
#pragma unroll
            for (int e = 0; e < 2; ++e)
                yt[j * 2 + e] = ytg_s[stage * 32 + j * 8 + q * 2 + e];

        if (lane == 0) MBARRIER_ARRIVE(sb + stage * 16 + 8);  // warp done with buffer

        // producer lives in the TRAILING half (warp 4) so its empty-wait is short
        if (tid == 128 && t + NSTAGE < NMT) {
            MBARRIER_WAIT_PARITY(sb + stage * 16 + 8, phase);
            MBARRIER_EXPECT_TX(sb + stage * 16, B_BLOB + 512);
            bulk_g2s(sb + SM_B + stage * B_BLOB, gB + (size_t)(t + NSTAGE) * B_BLOB,
                     B_BLOB, sb + stage * 16);
            bulk_g2s(sb + SM_YTG + stage * 512, gY + (t + NSTAGE) * TM, 512,
                     sb + stage * 16);
        }

        // ---- per-thread online softmax (rows r0 = wid*16+r, r1 = +8) ----
        float l0[8], l1[8];
#pragma unroll
        for (int j = 0; j < 4; ++j)
#pragma unroll
            for (int e = 0; e < 2; ++e) {
                float yy = yt[j * 2 + e].x;
                l0[j * 2 + e] = acc[j][e] - yy;
                l1[j * 2 + e] = acc[j][2 + e] - yy;
            }
        row_update(st0, l0, yt);
        row_update(st1, l1, yt);

        if (++stage == NSTAGE) { stage = 0; phase ^= 1; }
    }

    // ---- merge across quad (lanes sharing the same rows), write out ----
    row_merge(st0, 1); row_merge(st0, 2);
    row_merge(st1, 1); row_merge(st1, 2);

    if (q == 0) {
        size_t base = (size_t)b * 3 * NN;
        int na = n0 + wid * 16 + r;
        int nb = na + 8;
        float ia = 1.f / st0.s, ib = 1.f / st1.s;
        out[base + na] = st0.o0 * ia;
        out[base + NN + na] = st0.o1 * ia;
        out[base + 2 * NN + na] = st0.o2 * ia;
        out[base + nb] = st1.o0 * ib;
        out[base + NN + nb] = st1.o1 * ib;
        out[base + 2 * NN + nb] = st1.o2 * ib;
    }
}

extern "C" void kernel_launch(void* const* d_in, const int* in_sizes, int n_in,
                              void* d_out, int out_size) {
    // inputs per metadata: [0]=src (unused), [1]=tgt, [2]=src_emb, [3]=tgt_emb
    const float* tgt     = (const float*)d_in[1];
    const float* src_emb = (const float*)d_in[2];
    const float* tgt_emb = (const float*)d_in[3];
    float* out = (float*)d_out;

    cudaFuncSetAttribute(convB_kernel,
                         cudaFuncAttributeMaxDynamicSharedMemorySize, CONVB_SMEM);
    cudaFuncSetAttribute(corr_mma_kernel,
                         cudaFuncAttributeMaxDynamicSharedMemorySize, SMEM_MAIN);

    convB_kernel<<<dim3(NMT, BB), 256, CONVB_SMEM>>>(tgt_emb, tgt);
    corr_mma_kernel<<<dim3(NN / TN, BB), 256, SMEM_MAIN>>>(src_emb, out);
}